// round 9
// baseline (speedup 1.0000x reference)
#include <cuda_runtime.h>
#include <cstddef>

#define HID   128
#define NMAX  50000
#define CAP   64        // per-node bucket capacity (max degree ~40; R6/R8-validated)
#define XPAD  68        // padded row stride of transposed X tile (floats)
#define PDEPTH 4        // cp.async pipeline depth (rows in flight per warp)

// ---- device-global scratch (sanctioned alloc-free mechanism) ----
__device__ float g_H1[(size_t)NMAX * HID];        // relu(nf @ W1 + b1)
__device__ float g_pooled[(size_t)NMAX * HID];    // segment-sum result
__device__ int   g_cnt[NMAX];                     // bucket counts (self-cleaned by pool)
__device__ int2  g_pedge[(size_t)NMAX * CAP];     // (src, norm-bits) buckets keyed by tgt

// ---------------------------------------------------------------------------
// GEMM: Y = relu(X @ W + b) [+ res]. Exact R3 FFMA2 core (verified fast).
// DO_FILL adds R8's bucket-fill tail (measured nearly free under GEMM math).
// ---------------------------------------------------------------------------
template <bool RESIDUAL, bool DO_FILL>
__global__ __launch_bounds__(256) void gemm_relu_kernel(
    const float* __restrict__ X, const float* __restrict__ W,
    const float* __restrict__ b, const float* __restrict__ res,
    float* __restrict__ Y, int nrows,
    const int* __restrict__ src, const int* __restrict__ tgt,
    const float* __restrict__ norm, int nedges)
{
    extern __shared__ float smem[];
    float* ws  = smem;                // [128][128]  64KB
    float* xst = smem + HID * HID;    // [128][XPAD] (transposed tile)

    const int tid  = threadIdx.x;
    const int row0 = blockIdx.x * 64;

    #pragma unroll
    for (int i = tid; i < HID * HID; i += 256) ws[i] = W[i];

    #pragma unroll
    for (int i = tid; i < 64 * HID; i += 256) {
        int r = i >> 7, k = i & 127;
        int gr = row0 + r;
        xst[k * XPAD + r] = (gr < nrows) ? X[(size_t)gr * HID + k] : 0.f;
    }
    __syncthreads();

    const int cg = tid & 31;
    const int rg = tid >> 5;
    const int c0 = cg << 2;
    const int r0 = rg << 3;

    unsigned long long acc[4][4];
    #pragma unroll
    for (int p = 0; p < 4; p++)
        #pragma unroll
        for (int c = 0; c < 4; c++) acc[p][c] = 0ull;

    #pragma unroll 4
    for (int k = 0; k < HID; k++) {
        ulonglong2 xa = *(const ulonglong2*)&xst[k * XPAD + r0];
        ulonglong2 xb = *(const ulonglong2*)&xst[k * XPAD + r0 + 4];
        unsigned long long xp[4] = {xa.x, xa.y, xb.x, xb.y};

        float4 wv = *(const float4*)&ws[k * HID + c0];
        unsigned long long wd[4];
        asm("mov.b64 %0, {%1, %1};" : "=l"(wd[0]) : "f"(wv.x));
        asm("mov.b64 %0, {%1, %1};" : "=l"(wd[1]) : "f"(wv.y));
        asm("mov.b64 %0, {%1, %1};" : "=l"(wd[2]) : "f"(wv.z));
        asm("mov.b64 %0, {%1, %1};" : "=l"(wd[3]) : "f"(wv.w));

        #pragma unroll
        for (int p = 0; p < 4; p++)
            #pragma unroll
            for (int c = 0; c < 4; c++)
                asm("fma.rn.f32x2 %0, %1, %2, %0;"
                    : "+l"(acc[p][c]) : "l"(xp[p]), "l"(wd[c]));
    }

    float4 bias = *(const float4*)&b[c0];
    #pragma unroll
    for (int p = 0; p < 4; p++) {
        float lo[4], hi[4];
        #pragma unroll
        for (int c = 0; c < 4; c++)
            asm("mov.b64 {%0, %1}, %2;" : "=f"(lo[c]), "=f"(hi[c]) : "l"(acc[p][c]));

        int rowA = row0 + r0 + 2 * p;
        int rowB = rowA + 1;
        if (rowA < nrows) {
            float4 o;
            o.x = fmaxf(lo[0] + bias.x, 0.f);
            o.y = fmaxf(lo[1] + bias.y, 0.f);
            o.z = fmaxf(lo[2] + bias.z, 0.f);
            o.w = fmaxf(lo[3] + bias.w, 0.f);
            if (RESIDUAL) {
                float4 rr = *(const float4*)&res[(size_t)rowA * HID + c0];
                o.x += rr.x; o.y += rr.y; o.z += rr.z; o.w += rr.w;
            }
            *(float4*)&Y[(size_t)rowA * HID + c0] = o;
        }
        if (rowB < nrows) {
            float4 o;
            o.x = fmaxf(hi[0] + bias.x, 0.f);
            o.y = fmaxf(hi[1] + bias.y, 0.f);
            o.z = fmaxf(hi[2] + bias.z, 0.f);
            o.w = fmaxf(hi[3] + bias.w, 0.f);
            if (RESIDUAL) {
                float4 rr = *(const float4*)&res[(size_t)rowB * HID + c0];
                o.x += rr.x; o.y += rr.y; o.z += rr.z; o.w += rr.w;
            }
            *(float4*)&Y[(size_t)rowB * HID + c0] = o;
        }
    }

    if (DO_FILL) {
        // Bucket fill tail (overlaps other blocks' GEMM math; R8-measured ~free).
        // g_cnt zero on entry: BSS at load; pool self-cleans every replay.
        int stride = gridDim.x * 256;
        for (int e = blockIdx.x * 256 + tid; e < nedges; e += stride) {
            int t  = tgt[e];
            int sl = atomicAdd(&g_cnt[t], 1);
            if (sl < CAP)
                g_pedge[(size_t)t * CAP + sl] =
                    make_int2(src[e], __float_as_int(norm[e]));
        }
    }
}

// ---------------------------------------------------------------------------
// cp.async helpers
// ---------------------------------------------------------------------------
__device__ __forceinline__ void cp_async16(unsigned sa, const void* gp)
{
    asm volatile("cp.async.cg.shared.global [%0], [%1], 16;"
                 :: "r"(sa), "l"(gp) : "memory");
}
__device__ __forceinline__ void cp_commit()
{
    asm volatile("cp.async.commit_group;" ::: "memory");
}
__device__ __forceinline__ void cp_wait_clamped(int pend)
{
    // wait until <= pend groups outstanding (immediate must be constant)
    if (pend >= PDEPTH - 1) {
        asm volatile("cp.async.wait_group 3;" ::: "memory");
    } else if (pend == 2) {
        asm volatile("cp.async.wait_group 2;" ::: "memory");
    } else if (pend == 1) {
        asm volatile("cp.async.wait_group 1;" ::: "memory");
    } else {
        asm volatile("cp.async.wait_group 0;" ::: "memory");
    }
}

// ---------------------------------------------------------------------------
// Pool: warp per node, cp.async row pipeline (depth PDEPTH).
//  - payloads for the whole node loaded in 2 coalesced int2 LDGs, shfl'd out
//  - each lane cp.asyncs its own 16B of each H1 row (no cross-lane -> no sync)
//  - 16KB static smem -> 8 blocks/SM, ~100% occupancy; MLP is structural
// Self-cleans g_cnt for the next graph replay.
// ---------------------------------------------------------------------------
__global__ __launch_bounds__(256) void pool_kernel(int nnodes)
{
    __shared__ float4 pipe[8][PDEPTH][32];   // 16KB

    const int w    = threadIdx.x >> 5;
    const int lane = threadIdx.x & 31;
    const int n    = blockIdx.x * 8 + w;
    if (n >= nnodes) return;

    int cnt = g_cnt[n];
    if (lane == 0) g_cnt[n] = 0;             // reset for next replay
    cnt = (cnt < CAP) ? cnt : CAP;

    // Whole-node payload in 2 coalesced loads (bucket array always in-bounds)
    const int2* bk = g_pedge + (size_t)n * CAP;
    int2 pe0 = bk[lane];
    int2 pe1 = bk[lane + 32];

    const unsigned sbase = (unsigned)__cvta_generic_to_shared(&pipe[w][0][lane]);
    const unsigned mask  = 0xffffffffu;

    // Prologue: issue rows 0..min(PDEPTH,cnt)-1
    int npro = (cnt < PDEPTH) ? cnt : PDEPTH;
    for (int j = 0; j < npro; j++) {
        int sj = __shfl_sync(mask, (j < 32) ? pe0.x : pe1.x, j & 31);
        cp_async16(sbase + (unsigned)(j & (PDEPTH - 1)) * 512u,
                   &g_H1[(size_t)sj * HID + lane * 4]);
        cp_commit();
    }

    float4 acc = make_float4(0.f, 0.f, 0.f, 0.f);
    for (int j = 0; j < cnt; j++) {
        cp_wait_clamped(cnt - 1 - j);        // row j's group retired

        float nm = __shfl_sync(mask,
            __int_as_float((j < 32) ? pe0.y : pe1.y), j & 31);
        float4 v = pipe[w][j & (PDEPTH - 1)][lane];
        acc.x = fmaf(nm, v.x, acc.x);
        acc.y = fmaf(nm, v.y, acc.y);
        acc.z = fmaf(nm, v.z, acc.z);
        acc.w = fmaf(nm, v.w, acc.w);

        int jn = j + PDEPTH;
        if (jn < cnt) {
            int sj = __shfl_sync(mask, (jn < 32) ? pe0.x : pe1.x, jn & 31);
            cp_async16(sbase + (unsigned)(jn & (PDEPTH - 1)) * 512u,
                       &g_H1[(size_t)sj * HID + lane * 4]);
            cp_commit();
        }
    }

    *(float4*)&g_pooled[(size_t)n * HID + lane * 4] = acc;
}

// ---------------------------------------------------------------------------
// Launch: 3 kernels, single stream.
// ---------------------------------------------------------------------------
extern "C" void kernel_launch(void* const* d_in, const int* in_sizes, int n_in,
                              void* d_out, int out_size)
{
    const float* nf   = (const float*)d_in[0];
    const int*   src  = (const int*)d_in[1];
    const int*   tgt  = (const int*)d_in[2];
    const float* norm = (const float*)d_in[3];
    const float* W1   = (const float*)d_in[4];
    const float* b1   = (const float*)d_in[5];
    const float* W2   = (const float*)d_in[6];
    const float* b2   = (const float*)d_in[7];
    float*       out  = (float*)d_out;

    const int nnodes = in_sizes[0] / HID;
    const int nedges = in_sizes[1];

    const size_t smem = (size_t)(HID * HID + HID * XPAD) * sizeof(float); // ~98KB
    cudaFuncSetAttribute(gemm_relu_kernel<false, true>,
                         cudaFuncAttributeMaxDynamicSharedMemorySize, (int)smem);
    cudaFuncSetAttribute(gemm_relu_kernel<true, false>,
                         cudaFuncAttributeMaxDynamicSharedMemorySize, (int)smem);

    float *H1 = nullptr, *pooled = nullptr;
    cudaGetSymbolAddress((void**)&H1, g_H1);
    cudaGetSymbolAddress((void**)&pooled, g_pooled);

    const int gblocks = (nnodes + 63) / 64;

    // Layer 1: H1 = relu(nf @ W1 + b1); tail fills edge buckets (R8 pattern).
    gemm_relu_kernel<false, true><<<gblocks, 256, smem>>>(
        nf, W1, b1, nullptr, H1, nnodes, src, tgt, norm, nedges);

    // Pool: pooled[n] = sum norm * H1[src]  (cp.async pipelined, high occ)
    pool_kernel<<<(nnodes + 7) / 8, 256>>>(nnodes);

    // Layer 2: out = relu(pooled @ W2 + b2) + nf
    gemm_relu_kernel<true, false><<<gblocks, 256, smem>>>(
        pooled, W2, b2, nf, out, nnodes, nullptr, nullptr, nullptr, 0);
}

// round 10
// speedup vs baseline: 1.1978x; 1.1978x over previous
#include <cuda_runtime.h>
#include <cstddef>

#define HID   128
#define NMAX  50000
#define EMAX  800000
#define XPAD  68        // padded row stride of transposed X tile (floats)

// ---- device-global scratch (sanctioned alloc-free mechanism) ----
__device__ float g_H1[(size_t)NMAX * HID];       // relu(nf @ W1 + b1)
__device__ float g_pooled[(size_t)NMAX * HID];   // segment-sum result
__device__ int   g_cnt[NMAX];                    // per-node edge count (self-cleaned by pool)
__device__ int   g_off[NMAX];                    // CSR offsets
__device__ int   g_cur[NMAX];                    // fill cursors
__device__ int   g_psrc[EMAX];                   // src reordered by tgt
__device__ float g_pnorm[EMAX];                  // norm reordered by tgt

// ---------------------------------------------------------------------------
// GEMM: Y = relu(X @ W + b) [+ res]. Exact R3 FFMA2 core — stable ~50us in
// every measurement across rounds. NO fused tails (R9 showed they cost ~40us).
// ---------------------------------------------------------------------------
template <bool RESIDUAL>
__global__ __launch_bounds__(256) void gemm_relu_kernel(
    const float* __restrict__ X, const float* __restrict__ W,
    const float* __restrict__ b, const float* __restrict__ res,
    float* __restrict__ Y, int nrows)
{
    extern __shared__ float smem[];
    float* ws  = smem;                // [128][128]  64KB
    float* xst = smem + HID * HID;    // [128][XPAD] (transposed tile)

    const int tid  = threadIdx.x;
    const int row0 = blockIdx.x * 64;

    #pragma unroll
    for (int i = tid; i < HID * HID; i += 256) ws[i] = W[i];

    #pragma unroll
    for (int i = tid; i < 64 * HID; i += 256) {
        int r = i >> 7, k = i & 127;
        int gr = row0 + r;
        xst[k * XPAD + r] = (gr < nrows) ? X[(size_t)gr * HID + k] : 0.f;
    }
    __syncthreads();

    const int cg = tid & 31;
    const int rg = tid >> 5;
    const int c0 = cg << 2;
    const int r0 = rg << 3;

    unsigned long long acc[4][4];
    #pragma unroll
    for (int p = 0; p < 4; p++)
        #pragma unroll
        for (int c = 0; c < 4; c++) acc[p][c] = 0ull;

    #pragma unroll 4
    for (int k = 0; k < HID; k++) {
        ulonglong2 xa = *(const ulonglong2*)&xst[k * XPAD + r0];
        ulonglong2 xb = *(const ulonglong2*)&xst[k * XPAD + r0 + 4];
        unsigned long long xp[4] = {xa.x, xa.y, xb.x, xb.y};

        float4 wv = *(const float4*)&ws[k * HID + c0];
        unsigned long long wd[4];
        asm("mov.b64 %0, {%1, %1};" : "=l"(wd[0]) : "f"(wv.x));
        asm("mov.b64 %0, {%1, %1};" : "=l"(wd[1]) : "f"(wv.y));
        asm("mov.b64 %0, {%1, %1};" : "=l"(wd[2]) : "f"(wv.z));
        asm("mov.b64 %0, {%1, %1};" : "=l"(wd[3]) : "f"(wv.w));

        #pragma unroll
        for (int p = 0; p < 4; p++)
            #pragma unroll
            for (int c = 0; c < 4; c++)
                asm("fma.rn.f32x2 %0, %1, %2, %0;"
                    : "+l"(acc[p][c]) : "l"(xp[p]), "l"(wd[c]));
    }

    float4 bias = *(const float4*)&b[c0];
    #pragma unroll
    for (int p = 0; p < 4; p++) {
        float lo[4], hi[4];
        #pragma unroll
        for (int c = 0; c < 4; c++)
            asm("mov.b64 {%0, %1}, %2;" : "=f"(lo[c]), "=f"(hi[c]) : "l"(acc[p][c]));

        int rowA = row0 + r0 + 2 * p;
        int rowB = rowA + 1;
        if (rowA < nrows) {
            float4 o;
            o.x = fmaxf(lo[0] + bias.x, 0.f);
            o.y = fmaxf(lo[1] + bias.y, 0.f);
            o.z = fmaxf(lo[2] + bias.z, 0.f);
            o.w = fmaxf(lo[3] + bias.w, 0.f);
            if (RESIDUAL) {
                float4 rr = *(const float4*)&res[(size_t)rowA * HID + c0];
                o.x += rr.x; o.y += rr.y; o.z += rr.z; o.w += rr.w;
            }
            *(float4*)&Y[(size_t)rowA * HID + c0] = o;
        }
        if (rowB < nrows) {
            float4 o;
            o.x = fmaxf(hi[0] + bias.x, 0.f);
            o.y = fmaxf(hi[1] + bias.y, 0.f);
            o.z = fmaxf(hi[2] + bias.z, 0.f);
            o.w = fmaxf(hi[3] + bias.w, 0.f);
            if (RESIDUAL) {
                float4 rr = *(const float4*)&res[(size_t)rowB * HID + c0];
                o.x += rr.x; o.y += rr.y; o.z += rr.z; o.w += rr.w;
            }
            *(float4*)&Y[(size_t)rowB * HID + c0] = o;
        }
    }
}

// ---------------------------------------------------------------------------
// Histogram (R3-exact; g_cnt zero on entry — BSS at load / pool self-clean)
// ---------------------------------------------------------------------------
__global__ void hist_kernel(const int* __restrict__ tgt, int nedges)
{
    int e = blockIdx.x * blockDim.x + threadIdx.x;
    if (e < nedges) atomicAdd(&g_cnt[tgt[e]], 1);
}

// ---------------------------------------------------------------------------
// Single-block exclusive scan of g_cnt -> g_off / g_cur (1024 threads).
// ---------------------------------------------------------------------------
__global__ __launch_bounds__(1024) void scan_offsets_kernel(int nnodes)
{
    __shared__ int warpsum[32];
    const int t = threadIdx.x;
    const int per = (nnodes + 1023) >> 10;
    const int begin = t * per;
    const int end = (begin + per < nnodes) ? begin + per : nnodes;

    int local = 0;
    for (int n = begin; n < end; n++) local += g_cnt[n];

    const int lane = t & 31, wid = t >> 5;
    int v = local;
    #pragma unroll
    for (int d = 1; d < 32; d <<= 1) {
        int u = __shfl_up_sync(0xffffffffu, v, d);
        if (lane >= d) v += u;
    }
    if (lane == 31) warpsum[wid] = v;
    __syncthreads();
    if (wid == 0) {
        int w = warpsum[lane];
        #pragma unroll
        for (int d = 1; d < 32; d <<= 1) {
            int u = __shfl_up_sync(0xffffffffu, w, d);
            if (lane >= d) w += u;
        }
        warpsum[lane] = w;
    }
    __syncthreads();

    int excl = v - local + ((wid > 0) ? warpsum[wid - 1] : 0);
    for (int n = begin; n < end; n++) {
        g_off[n] = excl;
        g_cur[n] = excl;
        excl += g_cnt[n];
    }
}

// ---------------------------------------------------------------------------
// Fill (R3-exact scalar version — measured 15-18us, cheaper than fused tails)
// ---------------------------------------------------------------------------
__global__ void fill_kernel(const int* __restrict__ src,
                            const int* __restrict__ tgt,
                            const float* __restrict__ norm, int nedges)
{
    int e = blockIdx.x * blockDim.x + threadIdx.x;
    if (e >= nedges) return;
    int t = tgt[e];
    int pos = atomicAdd(&g_cur[t], 1);
    g_psrc[pos]  = src[e];
    g_pnorm[pos] = norm[e];
}

// ---------------------------------------------------------------------------
// Pool: TWO nodes per warp, interleaved. Each node's chain keeps R3's exact
// rolling 1-deep form (ptxas-friendly); interleaving two independent chains
// doubles per-warp loads in flight. Lane l owns floats [4l, 4l+4).
// Self-cleans g_cnt for the next graph replay.
// ---------------------------------------------------------------------------
__device__ __forceinline__ float4 h1row(int s, int lane)
{
    return *(const float4*)&g_H1[(size_t)s * HID + lane * 4];
}

__device__ __forceinline__ void fma4(float4& a, float n, const float4& v)
{
    a.x = fmaf(n, v.x, a.x);
    a.y = fmaf(n, v.y, a.y);
    a.z = fmaf(n, v.z, a.z);
    a.w = fmaf(n, v.w, a.w);
}

// R3-exact rolling accumulate over [off+j0, off+cnt)
__device__ __forceinline__ void roll_tail(float4& acc, int off, int j0, int cnt,
                                          int lane)
{
    if (j0 >= cnt) return;
    int   s  = g_psrc[off + j0];
    float nm = g_pnorm[off + j0];
    float4 v = h1row(s, lane);
    for (int j = j0 + 1; j < cnt; j++) {
        int   s2  = g_psrc[off + j];
        float nm2 = g_pnorm[off + j];
        float4 v2 = h1row(s2, lane);
        fma4(acc, nm, v);
        v = v2; nm = nm2;
    }
    fma4(acc, nm, v);
}

__global__ __launch_bounds__(256) void pool_kernel(int nnodes)
{
    const int pair = blockIdx.x * 8 + (threadIdx.x >> 5);
    const int n0 = pair * 2;
    if (n0 >= nnodes) return;
    const int n1 = n0 + 1;
    const bool has1 = (n1 < nnodes);
    const int lane = threadIdx.x & 31;

    int off0 = g_off[n0];
    int c0   = g_cnt[n0];
    int off1 = has1 ? g_off[n1] : 0;
    int c1   = has1 ? g_cnt[n1] : 0;
    if (lane == 0) {
        g_cnt[n0] = 0;                 // reset for next replay
        if (has1) g_cnt[n1] = 0;
    }

    float4 acc0 = make_float4(0.f, 0.f, 0.f, 0.f);
    float4 acc1 = make_float4(0.f, 0.f, 0.f, 0.f);

    const int m = (c0 < c1) ? c0 : c1;
    if (m > 0) {
        // Two independent rolling chains, interleaved (2x MLP per warp)
        int   sa = g_psrc[off0];
        float na = g_pnorm[off0];
        float4 va = h1row(sa, lane);
        int   sb = g_psrc[off1];
        float nb = g_pnorm[off1];
        float4 vb = h1row(sb, lane);
        for (int j = 1; j < m; j++) {
            int   sa2 = g_psrc[off0 + j];
            float na2 = g_pnorm[off0 + j];
            float4 va2 = h1row(sa2, lane);
            int   sb2 = g_psrc[off1 + j];
            float nb2 = g_pnorm[off1 + j];
            float4 vb2 = h1row(sb2, lane);
            fma4(acc0, na, va);
            fma4(acc1, nb, vb);
            va = va2; na = na2;
            vb = vb2; nb = nb2;
        }
        fma4(acc0, na, va);
        fma4(acc1, nb, vb);
    }
    // Drain the longer chain (R3-exact rolling loop)
    roll_tail(acc0, off0, m, c0, lane);
    roll_tail(acc1, off1, m, c1, lane);

    *(float4*)&g_pooled[(size_t)n0 * HID + lane * 4] = acc0;
    if (has1)
        *(float4*)&g_pooled[(size_t)n1 * HID + lane * 4] = acc1;
}

// ---------------------------------------------------------------------------
// Launch: single stream, 6 kernels.
// ---------------------------------------------------------------------------
extern "C" void kernel_launch(void* const* d_in, const int* in_sizes, int n_in,
                              void* d_out, int out_size)
{
    const float* nf   = (const float*)d_in[0];
    const int*   src  = (const int*)d_in[1];
    const int*   tgt  = (const int*)d_in[2];
    const float* norm = (const float*)d_in[3];
    const float* W1   = (const float*)d_in[4];
    const float* b1   = (const float*)d_in[5];
    const float* W2   = (const float*)d_in[6];
    const float* b2   = (const float*)d_in[7];
    float*       out  = (float*)d_out;

    const int nnodes = in_sizes[0] / HID;
    const int nedges = in_sizes[1];

    const size_t smem = (size_t)(HID * HID + HID * XPAD) * sizeof(float);
    cudaFuncSetAttribute(gemm_relu_kernel<false>,
                         cudaFuncAttributeMaxDynamicSharedMemorySize, (int)smem);
    cudaFuncSetAttribute(gemm_relu_kernel<true>,
                         cudaFuncAttributeMaxDynamicSharedMemorySize, (int)smem);

    float *H1 = nullptr, *pooled = nullptr;
    cudaGetSymbolAddress((void**)&H1, g_H1);
    cudaGetSymbolAddress((void**)&pooled, g_pooled);

    const int gblocks = (nnodes + 63) / 64;

    // GEMM1: H1 = relu(nf @ W1 + b1)
    gemm_relu_kernel<false><<<gblocks, 256, smem>>>(nf, W1, b1, nullptr, H1, nnodes);

    // CSR build: hist -> scan -> fill
    hist_kernel<<<(nedges + 255) / 256, 256>>>(tgt, nedges);
    scan_offsets_kernel<<<1, 1024>>>(nnodes);
    fill_kernel<<<(nedges + 255) / 256, 256>>>(src, tgt, norm, nedges);

    // Pool: pooled[n] = sum norm * H1[src]  (2 nodes/warp, interleaved chains)
    const int npairs = (nnodes + 1) / 2;
    pool_kernel<<<(npairs + 7) / 8, 256>>>(nnodes);

    // GEMM2: out = relu(pooled @ W2 + b2) + nf
    gemm_relu_kernel<true><<<gblocks, 256, smem>>>(pooled, W2, b2, nf, out, nnodes);
}